// round 1
// baseline (speedup 1.0000x reference)
#include <cuda_runtime.h>
#include <cuda_bf16.h>
#include <math.h>

#define NN 8192
#define NE 65536
#define ET (NN + NE)          // 73728 edges incl. self loops
#define DMAX 3584
#define NEG_SLOPE 0.2f
#define LN_EPS 1e-5f

// ---------------- scratch (no cudaMalloc allowed) ----------------
__device__ float g_bufA[(size_t)NN * DMAX];   // layer input (post-LN)
__device__ float g_bufH[(size_t)NN * DMAX];   // h = X @ W
__device__ float g_bufO[(size_t)NN * DMAX];   // aggregated output (pre-LN)
__device__ float g_alpha[(size_t)ET * 8];     // per-edge exp values
__device__ float g_m[NN * 8];
__device__ float g_z[NN * 8];
__device__ float g_als[NN * 8];
__device__ float g_ald[NN * 8];
__device__ int   g_src[ET];
__device__ int   g_dst[ET];
__device__ int   g_deg[NN];
__device__ int   g_rowptr[NN + 1];
__device__ int   g_cursor[NN];
__device__ int   g_srcs[ET];                  // CSR-by-dst: source node
__device__ int   g_eids[ET];                  // CSR-by-dst: original edge id

// ---------------- small utility kernels ----------------
__global__ void fill_f(float* p, float v, int n) {
    int i = blockIdx.x * blockDim.x + threadIdx.x;
    if (i < n) p[i] = v;
}
__global__ void fill_i(int* p, int v, int n) {
    int i = blockIdx.x * blockDim.x + threadIdx.x;
    if (i < n) p[i] = v;
}

__global__ void build_edges(const int* __restrict__ ei, int* src, int* dst, int* deg) {
    int i = blockIdx.x * blockDim.x + threadIdx.x;
    if (i >= ET) return;
    int s, d;
    if (i < NE) { s = ei[i]; d = ei[NE + i]; }
    else        { s = i - NE; d = i - NE; }
    src[i] = s; dst[i] = d;
    atomicAdd(&deg[d], 1);
}

// single-block exclusive scan over 8192 degrees (1024 threads x 8)
__global__ void scan_deg(const int* __restrict__ deg, int* rowptr, int* cursor) {
    __shared__ int sh[1024];
    int tid = threadIdx.x;
    int vals[8];
    int s = 0;
#pragma unroll
    for (int j = 0; j < 8; j++) { vals[j] = deg[tid * 8 + j]; s += vals[j]; }
    sh[tid] = s;
    __syncthreads();
    // Hillis-Steele inclusive scan
    for (int off = 1; off < 1024; off <<= 1) {
        int t = 0;
        if (tid >= off) t = sh[tid - off];
        __syncthreads();
        if (tid >= off) sh[tid] += t;
        __syncthreads();
    }
    int base = (tid == 0) ? 0 : sh[tid - 1];
    int run = base;
#pragma unroll
    for (int j = 0; j < 8; j++) {
        rowptr[tid * 8 + j] = run;
        cursor[tid * 8 + j] = run;
        run += vals[j];
    }
    if (tid == 1023) rowptr[NN] = run;
}

__global__ void scatter_edges(const int* __restrict__ src, const int* __restrict__ dst,
                              int* cursor, int* srcs, int* eids) {
    int i = blockIdx.x * blockDim.x + threadIdx.x;
    if (i >= ET) return;
    int pos = atomicAdd(&cursor[dst[i]], 1);
    srcs[pos] = src[i];
    eids[pos] = i;
}

// ---------------- SGEMM: C[M,N] = A[M,K] @ B[K,N] (row-major fp32) ----------------
// 128x128 block tile, BK=8, 256 threads, 8x8 per-thread microtile.
__global__ __launch_bounds__(256) void sgemm(const float* __restrict__ A,
                                             const float* __restrict__ B,
                                             float* __restrict__ C,
                                             int M, int N, int K) {
    __shared__ float As[8][128];
    __shared__ float Bs[8][128];
    int tid = threadIdx.x;
    int tx = tid & 15;        // 0..15  -> col group
    int ty = tid >> 4;        // 0..15  -> row group
    int bx = blockIdx.x, by = blockIdx.y;
    int row0 = by * 128;
    int col0 = bx * 128;

    int arow = tid >> 1;           // 0..127
    int acol = (tid & 1) * 4;      // 0 or 4
    int brow = tid >> 5;           // 0..7
    int bcol = (tid & 31) * 4;     // 0..124

    float acc[8][8];
#pragma unroll
    for (int i = 0; i < 8; i++)
#pragma unroll
        for (int j = 0; j < 8; j++) acc[i][j] = 0.f;

    for (int k0 = 0; k0 < K; k0 += 8) {
        // A tile: 128 rows x 8 cols (K divisible by 8, M by 128)
        float4 av = *(const float4*)(A + (size_t)(row0 + arow) * K + k0 + acol);
        As[acol + 0][arow] = av.x;
        As[acol + 1][arow] = av.y;
        As[acol + 2][arow] = av.z;
        As[acol + 3][arow] = av.w;
        // B tile: 8 rows x 128 cols, guard N
        float4 bv;
        int gcol = col0 + bcol;
        if (gcol + 3 < N) {
            bv = *(const float4*)(B + (size_t)(k0 + brow) * N + gcol);
        } else {
            bv.x = (gcol + 0 < N) ? B[(size_t)(k0 + brow) * N + gcol + 0] : 0.f;
            bv.y = (gcol + 1 < N) ? B[(size_t)(k0 + brow) * N + gcol + 1] : 0.f;
            bv.z = (gcol + 2 < N) ? B[(size_t)(k0 + brow) * N + gcol + 2] : 0.f;
            bv.w = 0.f;
        }
        *(float4*)&Bs[brow][bcol] = bv;
        __syncthreads();

#pragma unroll
        for (int k = 0; k < 8; k++) {
            float a[8], b[8];
            *(float4*)&a[0] = *(const float4*)&As[k][ty * 8];
            *(float4*)&a[4] = *(const float4*)&As[k][ty * 8 + 4];
            *(float4*)&b[0] = *(const float4*)&Bs[k][tx * 8];
            *(float4*)&b[4] = *(const float4*)&Bs[k][tx * 8 + 4];
#pragma unroll
            for (int i = 0; i < 8; i++)
#pragma unroll
                for (int j = 0; j < 8; j++) acc[i][j] += a[i] * b[j];
        }
        __syncthreads();
    }

#pragma unroll
    for (int i = 0; i < 8; i++) {
        int r = row0 + ty * 8 + i;
#pragma unroll
        for (int j = 0; j < 8; j++) {
            int c = col0 + tx * 8 + j;
            if (c < N) C[(size_t)r * N + c] = acc[i][j];
        }
    }
}

// ---------------- attention logits: warp per (node, head) ----------------
__global__ void attn_logits(const float* __restrict__ h,
                            const float* __restrict__ asrc,
                            const float* __restrict__ adst,
                            float* __restrict__ als, float* __restrict__ ald,
                            int H, int C) {
    int gw = (blockIdx.x * blockDim.x + threadIdx.x) >> 5;
    int lane = threadIdx.x & 31;
    if (gw >= NN * H) return;
    int n = gw / H, hd = gw % H;
    const float* hp = h + (size_t)n * H * C + (size_t)hd * C;
    const float* as = asrc + (size_t)hd * C;
    const float* ad = adst + (size_t)hd * C;
    float s = 0.f, d = 0.f;
    for (int c = lane; c < C; c += 32) {
        float v = hp[c];
        s += v * as[c];
        d += v * ad[c];
    }
#pragma unroll
    for (int o = 16; o; o >>= 1) {
        s += __shfl_xor_sync(0xFFFFFFFFu, s, o);
        d += __shfl_xor_sync(0xFFFFFFFFu, d, o);
    }
    if (lane == 0) { als[gw] = s; ald[gw] = d; }
}

__device__ __forceinline__ void atomicMaxF(float* addr, float val) {
    int* ia = (int*)addr;
    int old = *ia;
    while (__int_as_float(old) < val) {
        int assumed = old;
        old = atomicCAS(ia, assumed, __float_as_int(val));
        if (old == assumed) break;
    }
}

__global__ void edge_max(const float* __restrict__ als, const float* __restrict__ ald,
                         const int* __restrict__ src, const int* __restrict__ dst,
                         float* __restrict__ m, int H) {
    int i = blockIdx.x * blockDim.x + threadIdx.x;
    if (i >= ET * H) return;
    int e = i / H, hd = i - e * H;
    float v = als[src[e] * H + hd] + ald[dst[e] * H + hd];
    v = (v > 0.f) ? v : NEG_SLOPE * v;
    atomicMaxF(&m[dst[e] * H + hd], v);
}

__global__ void edge_exp(const float* __restrict__ als, const float* __restrict__ ald,
                         const int* __restrict__ src, const int* __restrict__ dst,
                         const float* __restrict__ m, float* __restrict__ z,
                         float* __restrict__ aex, int H) {
    int i = blockIdx.x * blockDim.x + threadIdx.x;
    if (i >= ET * H) return;
    int e = i / H, hd = i - e * H;
    float v = als[src[e] * H + hd] + ald[dst[e] * H + hd];
    v = (v > 0.f) ? v : NEG_SLOPE * v;
    float ex = expf(v - m[dst[e] * H + hd]);
    aex[(size_t)e * H + hd] = ex;
    atomicAdd(&z[dst[e] * H + hd], ex);
}

// ---------------- aggregation (CSR by dst) + bias + optional relu ----------------
__global__ __launch_bounds__(128) void aggregate(const float* __restrict__ h,
                                                 const float* __restrict__ aex,
                                                 const float* __restrict__ z,
                                                 const int* __restrict__ rowptr,
                                                 const int* __restrict__ srcs,
                                                 const int* __restrict__ eids,
                                                 const float* __restrict__ bias,
                                                 float* __restrict__ out,
                                                 int H, int C, int do_relu) {
    int n = blockIdx.x;
    int hd = blockIdx.y;
    int D = H * C;
    float acc[8];
#pragma unroll
    for (int j = 0; j < 8; j++) acc[j] = 0.f;

    int s = rowptr[n], e = rowptr[n + 1];
    for (int k = s; k < e; k++) {
        int sn = srcs[k];
        float al = aex[(size_t)eids[k] * H + hd];
        const float* hp = h + (size_t)sn * D + (size_t)hd * C;
#pragma unroll
        for (int j = 0; j < 8; j++) {
            int c = threadIdx.x + j * 128;
            if (c < C) acc[j] += al * hp[c];
        }
    }
    float invz = 1.f / (z[n * H + hd] + 1e-16f);
#pragma unroll
    for (int j = 0; j < 8; j++) {
        int c = threadIdx.x + j * 128;
        if (c < C) {
            float v = acc[j] * invz + bias[hd * C + c];
            if (do_relu) v = fmaxf(v, 0.f);
            out[(size_t)n * D + (size_t)hd * C + c] = v;
        }
    }
}

// ---------------- layernorm: block per row ----------------
__device__ __forceinline__ float warpSum(float v) {
#pragma unroll
    for (int o = 16; o; o >>= 1) v += __shfl_xor_sync(0xFFFFFFFFu, v, o);
    return v;
}

__global__ __launch_bounds__(256) void ln_kernel(const float* __restrict__ in,
                                                 const float* __restrict__ g,
                                                 const float* __restrict__ beta,
                                                 float* __restrict__ out, int D) {
    int n = blockIdx.x;
    const float* row = in + (size_t)n * D;
    float vals[14];
    float s = 0.f, sq = 0.f;
    int nit = (D + 255) / 256;
    for (int j = 0; j < nit; j++) {
        int c = threadIdx.x + j * 256;
        float v = (c < D) ? row[c] : 0.f;
        vals[j] = v;
        s += v;
        sq += v * v;
    }
    __shared__ float shs[8], shq[8];
    int wid = threadIdx.x >> 5, lane = threadIdx.x & 31;
    s = warpSum(s); sq = warpSum(sq);
    if (lane == 0) { shs[wid] = s; shq[wid] = sq; }
    __syncthreads();
    if (wid == 0) {
        s = (lane < 8) ? shs[lane] : 0.f;
        sq = (lane < 8) ? shq[lane] : 0.f;
        s = warpSum(s); sq = warpSum(sq);
        if (lane == 0) { shs[0] = s; shq[0] = sq; }
    }
    __syncthreads();
    float mean = shs[0] / D;
    float var = shq[0] / D - mean * mean;
    float inv = rsqrtf(var + LN_EPS);
    for (int j = 0; j < nit; j++) {
        int c = threadIdx.x + j * 256;
        if (c < D) out[(size_t)n * D + c] = (vals[j] - mean) * inv * g[c] + beta[c];
    }
}

// ---------------- driver ----------------
extern "C" void kernel_launch(void* const* d_in, const int* in_sizes, int n_in,
                              void* d_out, int out_size) {
    (void)in_sizes; (void)n_in; (void)out_size;
    const float* x = (const float*)d_in[0];
    const int* ei = (const int*)d_in[1];
    const float* W[4]  = {(const float*)d_in[2],  (const float*)d_in[8],
                          (const float*)d_in[14], (const float*)d_in[20]};
    const float* Asr[4] = {(const float*)d_in[3],  (const float*)d_in[9],
                           (const float*)d_in[15], (const float*)d_in[21]};
    const float* Ads[4] = {(const float*)d_in[4],  (const float*)d_in[10],
                           (const float*)d_in[16], (const float*)d_in[22]};
    const float* Bi[4]  = {(const float*)d_in[5],  (const float*)d_in[11],
                           (const float*)d_in[17], (const float*)d_in[23]};
    const float* G[3]   = {(const float*)d_in[6],  (const float*)d_in[12],
                           (const float*)d_in[18]};
    const float* Be[3]  = {(const float*)d_in[7],  (const float*)d_in[13],
                           (const float*)d_in[19]};

    static const int din[4] = {256, 3584, 3072, 2048};
    static const int Hh[4]  = {8, 8, 8, 1};
    static const int Cc[4]  = {448, 384, 256, 1000};

    float *bufA, *bufH, *bufO, *alpha, *m, *z, *als, *ald;
    int *src, *dst, *deg, *rowptr, *cursor, *srcs, *eids;
    cudaGetSymbolAddress((void**)&bufA, g_bufA);
    cudaGetSymbolAddress((void**)&bufH, g_bufH);
    cudaGetSymbolAddress((void**)&bufO, g_bufO);
    cudaGetSymbolAddress((void**)&alpha, g_alpha);
    cudaGetSymbolAddress((void**)&m, g_m);
    cudaGetSymbolAddress((void**)&z, g_z);
    cudaGetSymbolAddress((void**)&als, g_als);
    cudaGetSymbolAddress((void**)&ald, g_ald);
    cudaGetSymbolAddress((void**)&src, g_src);
    cudaGetSymbolAddress((void**)&dst, g_dst);
    cudaGetSymbolAddress((void**)&deg, g_deg);
    cudaGetSymbolAddress((void**)&rowptr, g_rowptr);
    cudaGetSymbolAddress((void**)&cursor, g_cursor);
    cudaGetSymbolAddress((void**)&srcs, g_srcs);
    cudaGetSymbolAddress((void**)&eids, g_eids);

    // ---- build CSR-by-dst (fixed graph; rebuilt each call for determinism) ----
    fill_i<<<(NN + 255) / 256, 256>>>(deg, 0, NN);
    build_edges<<<(ET + 255) / 256, 256>>>(ei, src, dst, deg);
    scan_deg<<<1, 1024>>>(deg, rowptr, cursor);
    scatter_edges<<<(ET + 255) / 256, 256>>>(src, dst, cursor, srcs, eids);

    const float* X = x;
    for (int l = 0; l < 4; l++) {
        int H = Hh[l], C = Cc[l], D = H * C, K = din[l];
        dim3 gg((D + 127) / 128, NN / 128);
        sgemm<<<gg, 256>>>(X, W[l], bufH, NN, D, K);

        int warps = NN * H;
        attn_logits<<<(warps * 32 + 255) / 256, 256>>>(bufH, Asr[l], Ads[l], als, ald, H, C);

        fill_f<<<(NN * H + 255) / 256, 256>>>(m, -1e30f, NN * H);
        fill_f<<<(NN * H + 255) / 256, 256>>>(z, 0.f, NN * H);
        edge_max<<<(ET * H + 255) / 256, 256>>>(als, ald, src, dst, m, H);
        edge_exp<<<(ET * H + 255) / 256, 256>>>(als, ald, src, dst, m, z, alpha, H);

        float* outp = (l == 3) ? (float*)d_out : bufO;
        aggregate<<<dim3(NN, H), 128>>>(bufH, alpha, z, rowptr, srcs, eids, Bi[l], outp,
                                        H, C, (l < 3) ? 1 : 0);
        if (l < 3) {
            ln_kernel<<<NN, 256>>>(bufO, G[l], Be[l], bufA, D);
            X = bufA;
        }
    }
}

// round 4
// speedup vs baseline: 2.4369x; 2.4369x over previous
#include <cuda_runtime.h>
#include <cuda_bf16.h>
#include <math.h>
#include <stdint.h>

#define NN 8192
#define NE 65536
#define ET (NN + NE)          // 73728 edges incl. self loops
#define DMAX 3584
#define NEG_SLOPE 0.2f
#define LN_EPS 1e-5f

// ---------------- scratch (no cudaMalloc allowed) ----------------
__device__ float g_bufA[(size_t)NN * DMAX];   // layer input (post-LN)
__device__ float g_bufH[(size_t)NN * DMAX];   // h = X @ W
__device__ float g_bufO[(size_t)NN * DMAX];   // aggregated output (pre-LN)
__device__ float g_alpha[(size_t)ET * 8];     // per-edge exp values
__device__ float g_m[NN * 8];
__device__ float g_z[NN * 8];
__device__ float g_als[NN * 8];
__device__ float g_ald[NN * 8];
__device__ int   g_src[ET];
__device__ int   g_dst[ET];
__device__ int   g_deg[NN];
__device__ int   g_rowptr[NN + 1];
__device__ int   g_cursor[NN];
__device__ int   g_srcs[ET];
__device__ int   g_eids[ET];
// bf16-split GEMM operands
__device__ __nv_bfloat16 g_Ah[(size_t)NN * DMAX];
__device__ __nv_bfloat16 g_Al[(size_t)NN * DMAX];
__device__ __nv_bfloat16 g_Bh[11010048];      // max Npad*K over layers (3072*3584)
__device__ __nv_bfloat16 g_Bl[11010048];

// ---------------- PTX helpers (baseline ISA only: sm_100 base target) ------
__device__ __forceinline__ uint32_t smem_u32(const void* p) {
    uint32_t a;
    asm("{ .reg .u64 t; cvta.to.shared.u64 t, %1; cvt.u32.u64 %0, t; }" : "=r"(a) : "l"(p));
    return a;
}
__device__ __forceinline__ void cp16(uint32_t dst, const void* src) {
    asm volatile("cp.async.cg.shared.global [%0], [%1], 16;" :: "r"(dst), "l"(src));
}
#define CP_COMMIT() asm volatile("cp.async.commit_group;" ::: "memory")
#define CP_WAIT(n) asm volatile("cp.async.wait_group %0;" :: "n"(n) : "memory")

__device__ __forceinline__ void ldm_x4(uint32_t& r0, uint32_t& r1, uint32_t& r2, uint32_t& r3,
                                       uint32_t addr) {
    asm volatile("ldmatrix.sync.aligned.m8n8.x4.shared.b16 {%0,%1,%2,%3}, [%4];"
                 : "=r"(r0), "=r"(r1), "=r"(r2), "=r"(r3) : "r"(addr));
}
__device__ __forceinline__ void mma16816(float* d, const uint32_t* a, const uint32_t* b) {
    asm volatile("mma.sync.aligned.m16n8k16.row.col.f32.bf16.bf16.f32 "
                 "{%0,%1,%2,%3}, {%4,%5,%6,%7}, {%8,%9}, {%0,%1,%2,%3};"
                 : "+f"(d[0]), "+f"(d[1]), "+f"(d[2]), "+f"(d[3])
                 : "r"(a[0]), "r"(a[1]), "r"(a[2]), "r"(a[3]), "r"(b[0]), "r"(b[1]));
}
// 16B-chunk XOR swizzle on a 128-row x 64B (4-chunk) tile: conflict-free ldmatrix
__device__ __forceinline__ uint32_t swz(int r, int c) {
    return (uint32_t)(r * 64 + ((c ^ ((r >> 1) & 3)) << 4));
}

// ---------------- bf16 split conversions ----------------
__global__ void convA(const float* __restrict__ x, __nv_bfloat16* __restrict__ hi,
                      __nv_bfloat16* __restrict__ lo, int n) {
    int i = blockIdx.x * blockDim.x + threadIdx.x;
    if (i >= n) return;
    float v = x[i];
    __nv_bfloat16 h = __float2bfloat16(v);
    hi[i] = h;
    lo[i] = __float2bfloat16(v - __bfloat162float(h));
}

// W [K,N] fp32 -> Bt_hi/lo [Npad,K] bf16 (transpose + split, zero-pad rows >= N)
__global__ void convBT(const float* __restrict__ W, __nv_bfloat16* __restrict__ bh,
                       __nv_bfloat16* __restrict__ bl, int K, int N) {
    __shared__ float tile[32][33];
    int k0 = blockIdx.x * 32, n0 = blockIdx.y * 32;
    int tx = threadIdx.x, ty = threadIdx.y;  // 32 x 8
#pragma unroll
    for (int i = 0; i < 4; i++) {
        int k = k0 + ty + i * 8;
        int n = n0 + tx;
        tile[ty + i * 8][tx] = (n < N) ? W[(size_t)k * N + n] : 0.f;
    }
    __syncthreads();
#pragma unroll
    for (int i = 0; i < 4; i++) {
        int n = n0 + ty + i * 8;
        int k = k0 + tx;
        float v = tile[tx][ty + i * 8];
        __nv_bfloat16 h = __float2bfloat16(v);
        bh[(size_t)n * K + k] = h;
        bl[(size_t)n * K + k] = __float2bfloat16(v - __bfloat162float(h));
    }
}

// ---------------- mma.sync bf16x3 GEMM: C[8192, Nreal] = A @ Bt^T -----------
// CTA tile 128x128, K-chunk 32, 8 warps (warp tile 32 rows x 64 cols).
// Stage: Ah(8K) Al(8K) Bh(8K) Bl(8K) = 32KB; double buffered = 64KB dynamic.
#define MM_ST 32768
#define MM_SMEM (2 * MM_ST)

__global__ __launch_bounds__(256, 1)
void gemm_mma_bf16x3(const __nv_bfloat16* __restrict__ Ah, const __nv_bfloat16* __restrict__ Al,
                     const __nv_bfloat16* __restrict__ Bh, const __nv_bfloat16* __restrict__ Bl,
                     float* __restrict__ C, int K, int Nreal) {
    extern __shared__ char smem[];
    const uint32_t sb = smem_u32(smem);
    const int tid = threadIdx.x;
    const int lane = tid & 31;
    const int wid = tid >> 5;
    const int wm = wid & 3;       // 4 warps over M (32 rows each)
    const int wn = wid >> 2;      // 2 warps over N (64 cols each)
    const int row0 = blockIdx.y * 128;
    const int n0 = blockIdx.x * 128;
    const int NC = K >> 5;

    float acc[2][8][4];
#pragma unroll
    for (int mt = 0; mt < 2; mt++)
#pragma unroll
        for (int nt = 0; nt < 8; nt++)
#pragma unroll
            for (int j = 0; j < 4; j++) acc[mt][nt][j] = 0.f;

    // --- async stage loader: each thread copies 8 x 16B ---
    const int lr = tid >> 2;        // 0..63 (row group base)
    const int lc = tid & 3;         // chunk 0..3
    {
        // prologue: stages 0 and 1
#pragma unroll
        for (int c = 0; c < 2; c++) {
            if (c < NC) {
                uint32_t st = sb + c * MM_ST;
                int k0 = c * 32;
#pragma unroll
                for (int j = 0; j < 2; j++) {
                    int r = lr + j * 64;
                    uint32_t so = swz(r, lc);
                    size_t ga = (size_t)(row0 + r) * K + k0 + lc * 8;
                    size_t gb = (size_t)(n0 + r) * K + k0 + lc * 8;
                    cp16(st + so, Ah + ga);
                    cp16(st + 8192 + so, Al + ga);
                    cp16(st + 16384 + so, Bh + gb);
                    cp16(st + 24576 + so, Bl + gb);
                }
                CP_COMMIT();
            }
        }
    }

    for (int c = 0; c < NC; c++) {
        const int buf = c & 1;
        if (c + 1 < NC) { CP_WAIT(1); } else { CP_WAIT(0); }
        __syncthreads();
        const uint32_t st = sb + buf * MM_ST;

#pragma unroll
        for (int ks = 0; ks < 2; ks++) {
            uint32_t ahf[2][4], alf[2][4], bhf[8][2], blf[8][2];
            const int g = lane >> 3;
            // A fragments: matrices (m0-7,k0-7),(m8-15,k0-7),(m0-7,k8-15),(m8-15,k8-15)
#pragma unroll
            for (int mt = 0; mt < 2; mt++) {
                int r = wm * 32 + mt * 16 + (lane & 7) + ((g & 1) << 3);
                int ch = ks * 2 + (g >> 1);
                uint32_t ad = st + swz(r, ch);
                ldm_x4(ahf[mt][0], ahf[mt][1], ahf[mt][2], ahf[mt][3], ad);
                ldm_x4(alf[mt][0], alf[mt][1], alf[mt][2], alf[mt][3], ad + 8192);
            }
            // B fragments: per pair of n8 tiles: (n0-7,k0-7),(n0-7,k8-15),(n8-15,k0-7),(n8-15,k8-15)
#pragma unroll
            for (int np = 0; np < 4; np++) {
                int r = wn * 64 + np * 16 + (lane & 7) + ((g >> 1) << 3);
                int ch = ks * 2 + (g & 1);
                uint32_t ad = st + 16384 + swz(r, ch);
                ldm_x4(bhf[np * 2][0], bhf[np * 2][1], bhf[np * 2 + 1][0], bhf[np * 2 + 1][1], ad);
                ldm_x4(blf[np * 2][0], blf[np * 2][1], blf[np * 2 + 1][0], blf[np * 2 + 1][1], ad + 8192);
            }
#pragma unroll
            for (int mt = 0; mt < 2; mt++)
#pragma unroll
                for (int nt = 0; nt < 8; nt++) {
                    mma16816(acc[mt][nt], ahf[mt], bhf[nt]);
                    mma16816(acc[mt][nt], ahf[mt], blf[nt]);
                    mma16816(acc[mt][nt], alf[mt], bhf[nt]);
                }
        }
        __syncthreads();
        if (c + 2 < NC) {
            uint32_t stn = sb + buf * MM_ST;
            int k0 = (c + 2) * 32;
#pragma unroll
            for (int j = 0; j < 2; j++) {
                int r = lr + j * 64;
                uint32_t so = swz(r, lc);
                size_t ga = (size_t)(row0 + r) * K + k0 + lc * 8;
                size_t gb = (size_t)(n0 + r) * K + k0 + lc * 8;
                cp16(stn + so, Ah + ga);
                cp16(stn + 8192 + so, Al + ga);
                cp16(stn + 16384 + so, Bh + gb);
                cp16(stn + 24576 + so, Bl + gb);
            }
            CP_COMMIT();
        }
    }

    // epilogue: write accumulators (fragment: c0,c1 row t/4; c2,c3 row t/4+8)
#pragma unroll
    for (int mt = 0; mt < 2; mt++) {
        int r = row0 + wm * 32 + mt * 16 + (lane >> 2);
#pragma unroll
        for (int nt = 0; nt < 8; nt++) {
            int cb = n0 + wn * 64 + nt * 8 + (lane & 3) * 2;
            if (cb < Nreal) {
                C[(size_t)r * Nreal + cb] = acc[mt][nt][0];
                C[(size_t)(r + 8) * Nreal + cb] = acc[mt][nt][2];
                if (cb + 1 < Nreal) {
                    C[(size_t)r * Nreal + cb + 1] = acc[mt][nt][1];
                    C[(size_t)(r + 8) * Nreal + cb + 1] = acc[mt][nt][3];
                }
            }
        }
    }
}

// ---------------- small utility kernels ----------------
__global__ void fill_mz(float* m, float* z, int n) {
    int i = blockIdx.x * blockDim.x + threadIdx.x;
    if (i < n) { m[i] = -1e30f; z[i] = 0.f; }
}
__global__ void fill_i(int* p, int v, int n) {
    int i = blockIdx.x * blockDim.x + threadIdx.x;
    if (i < n) p[i] = v;
}

__global__ void build_edges(const int* __restrict__ ei, int* src, int* dst, int* deg) {
    int i = blockIdx.x * blockDim.x + threadIdx.x;
    if (i >= ET) return;
    int s, d;
    if (i < NE) { s = ei[i]; d = ei[NE + i]; }
    else        { s = i - NE; d = i - NE; }
    src[i] = s; dst[i] = d;
    atomicAdd(&deg[d], 1);
}

__global__ void scan_deg(const int* __restrict__ deg, int* rowptr, int* cursor) {
    __shared__ int sh[1024];
    int tid = threadIdx.x;
    int vals[8];
    int s = 0;
#pragma unroll
    for (int j = 0; j < 8; j++) { vals[j] = deg[tid * 8 + j]; s += vals[j]; }
    sh[tid] = s;
    __syncthreads();
    for (int off = 1; off < 1024; off <<= 1) {
        int t = 0;
        if (tid >= off) t = sh[tid - off];
        __syncthreads();
        if (tid >= off) sh[tid] += t;
        __syncthreads();
    }
    int base = (tid == 0) ? 0 : sh[tid - 1];
    int run = base;
#pragma unroll
    for (int j = 0; j < 8; j++) {
        rowptr[tid * 8 + j] = run;
        cursor[tid * 8 + j] = run;
        run += vals[j];
    }
    if (tid == 1023) rowptr[NN] = run;
}

__global__ void scatter_edges(const int* __restrict__ src, const int* __restrict__ dst,
                              int* cursor, int* srcs, int* eids) {
    int i = blockIdx.x * blockDim.x + threadIdx.x;
    if (i >= ET) return;
    int pos = atomicAdd(&cursor[dst[i]], 1);
    srcs[pos] = src[i];
    eids[pos] = i;
}

// ---------------- attention logits: warp per (node, head) ----------------
__global__ void attn_logits(const float* __restrict__ h,
                            const float* __restrict__ asrc,
                            const float* __restrict__ adst,
                            float* __restrict__ als, float* __restrict__ ald,
                            int H, int C) {
    int gw = (blockIdx.x * blockDim.x + threadIdx.x) >> 5;
    int lane = threadIdx.x & 31;
    if (gw >= NN * H) return;
    int n = gw / H, hd = gw % H;
    const float* hp = h + (size_t)n * H * C + (size_t)hd * C;
    const float* as = asrc + (size_t)hd * C;
    const float* ad = adst + (size_t)hd * C;
    float s = 0.f, d = 0.f;
    for (int c = lane; c < C; c += 32) {
        float v = hp[c];
        s += v * as[c];
        d += v * ad[c];
    }
#pragma unroll
    for (int o = 16; o; o >>= 1) {
        s += __shfl_xor_sync(0xFFFFFFFFu, s, o);
        d += __shfl_xor_sync(0xFFFFFFFFu, d, o);
    }
    if (lane == 0) { als[gw] = s; ald[gw] = d; }
}

__device__ __forceinline__ void atomicMaxF(float* addr, float val) {
    int* ia = (int*)addr;
    int old = *ia;
    while (__int_as_float(old) < val) {
        int assumed = old;
        old = atomicCAS(ia, assumed, __float_as_int(val));
        if (old == assumed) break;
    }
}

__global__ void edge_max(const float* __restrict__ als, const float* __restrict__ ald,
                         const int* __restrict__ src, const int* __restrict__ dst,
                         float* __restrict__ m, int H) {
    int i = blockIdx.x * blockDim.x + threadIdx.x;
    if (i >= ET * H) return;
    int e = i / H, hd = i - e * H;
    float v = als[src[e] * H + hd] + ald[dst[e] * H + hd];
    v = (v > 0.f) ? v : NEG_SLOPE * v;
    atomicMaxF(&m[dst[e] * H + hd], v);
}

__global__ void edge_exp(const float* __restrict__ als, const float* __restrict__ ald,
                         const int* __restrict__ src, const int* __restrict__ dst,
                         const float* __restrict__ m, float* __restrict__ z,
                         float* __restrict__ aex, int H) {
    int i = blockIdx.x * blockDim.x + threadIdx.x;
    if (i >= ET * H) return;
    int e = i / H, hd = i - e * H;
    float v = als[src[e] * H + hd] + ald[dst[e] * H + hd];
    v = (v > 0.f) ? v : NEG_SLOPE * v;
    float ex = expf(v - m[dst[e] * H + hd]);
    aex[(size_t)e * H + hd] = ex;
    atomicAdd(&z[dst[e] * H + hd], ex);
}

// ---------------- aggregation (CSR by dst) + bias + optional relu ----------------
__global__ __launch_bounds__(128) void aggregate(const float* __restrict__ h,
                                                 const float* __restrict__ aex,
                                                 const float* __restrict__ z,
                                                 const int* __restrict__ rowptr,
                                                 const int* __restrict__ srcs,
                                                 const int* __restrict__ eids,
                                                 const float* __restrict__ bias,
                                                 float* __restrict__ out,
                                                 int H, int C, int do_relu) {
    int n = blockIdx.x;
    int hd = blockIdx.y;
    int D = H * C;
    float acc[8];
#pragma unroll
    for (int j = 0; j < 8; j++) acc[j] = 0.f;

    int s = rowptr[n], e = rowptr[n + 1];
    for (int k = s; k < e; k++) {
        int sn = srcs[k];
        float al = aex[(size_t)eids[k] * H + hd];
        const float* hp = h + (size_t)sn * D + (size_t)hd * C;
#pragma unroll
        for (int j = 0; j < 8; j++) {
            int c = threadIdx.x + j * 128;
            if (c < C) acc[j] += al * hp[c];
        }
    }
    float invz = 1.f / (z[n * H + hd] + 1e-16f);
#pragma unroll
    for (int j = 0; j < 8; j++) {
        int c = threadIdx.x + j * 128;
        if (c < C) {
            float v = acc[j] * invz + bias[hd * C + c];
            if (do_relu) v = fmaxf(v, 0.f);
            out[(size_t)n * D + (size_t)hd * C + c] = v;
        }
    }
}

// ---------------- layernorm: block per row ----------------
__device__ __forceinline__ float warpSum(float v) {
#pragma unroll
    for (int o = 16; o; o >>= 1) v += __shfl_xor_sync(0xFFFFFFFFu, v, o);
    return v;
}

__global__ __launch_bounds__(256) void ln_kernel(const float* __restrict__ in,
                                                 const float* __restrict__ g,
                                                 const float* __restrict__ beta,
                                                 float* __restrict__ out, int D) {
    int n = blockIdx.x;
    const float* row = in + (size_t)n * D;
    float vals[14];
    float s = 0.f, sq = 0.f;
    int nit = (D + 255) / 256;
    for (int j = 0; j < nit; j++) {
        int c = threadIdx.x + j * 256;
        float v = (c < D) ? row[c] : 0.f;
        vals[j] = v;
        s += v;
        sq += v * v;
    }
    __shared__ float shs[8], shq[8];
    int wid = threadIdx.x >> 5, lane = threadIdx.x & 31;
    s = warpSum(s); sq = warpSum(sq);
    if (lane == 0) { shs[wid] = s; shq[wid] = sq; }
    __syncthreads();
    if (wid == 0) {
        s = (lane < 8) ? shs[lane] : 0.f;
        sq = (lane < 8) ? shq[lane] : 0.f;
        s = warpSum(s); sq = warpSum(sq);
        if (lane == 0) { shs[0] = s; shq[0] = sq; }
    }
    __syncthreads();
    float mean = shs[0] / D;
    float var = shq[0] / D - mean * mean;
    float inv = rsqrtf(var + LN_EPS);
    for (int j = 0; j < nit; j++) {
        int c = threadIdx.x + j * 256;
        if (c < D) out[(size_t)n * D + c] = (vals[j] - mean) * inv * g[c] + beta[c];
    }
}

// ---------------- driver ----------------
extern "C" void kernel_launch(void* const* d_in, const int* in_sizes, int n_in,
                              void* d_out, int out_size) {
    (void)in_sizes; (void)n_in; (void)out_size;
    const float* x = (const float*)d_in[0];
    const int* ei = (const int*)d_in[1];
    const float* W[4]  = {(const float*)d_in[2],  (const float*)d_in[8],
                          (const float*)d_in[14], (const float*)d_in[20]};
    const float* Asr[4] = {(const float*)d_in[3],  (const float*)d_in[9],
                           (const float*)d_in[15], (const float*)d_in[21]};
    const float* Ads[4] = {(const float*)d_in[4],  (const float*)d_in[10],
                           (const float*)d_in[16], (const float*)d_in[22]};
    const float* Bi[4]  = {(const float*)d_in[5],  (const float*)d_in[11],
                           (const float*)d_in[17], (const float*)d_in[23]};
    const float* G[3]   = {(const float*)d_in[6],  (const float*)d_in[12],
                           (const float*)d_in[18]};
    const float* Be[3]  = {(const float*)d_in[7],  (const float*)d_in[13],
                           (const float*)d_in[19]};

    static const int din[4]  = {256, 3584, 3072, 2048};
    static const int Hh[4]   = {8, 8, 8, 1};
    static const int Cc[4]   = {448, 384, 256, 1000};
    static const int Npad[4] = {3584, 3072, 2048, 1024};

    float *bufA, *bufH, *bufO, *alpha, *m, *z, *als, *ald;
    int *src, *dst, *deg, *rowptr, *cursor, *srcs, *eids;
    __nv_bfloat16 *Ahb, *Alb, *Bhb, *Blb;
    cudaGetSymbolAddress((void**)&bufA, g_bufA);
    cudaGetSymbolAddress((void**)&bufH, g_bufH);
    cudaGetSymbolAddress((void**)&bufO, g_bufO);
    cudaGetSymbolAddress((void**)&alpha, g_alpha);
    cudaGetSymbolAddress((void**)&m, g_m);
    cudaGetSymbolAddress((void**)&z, g_z);
    cudaGetSymbolAddress((void**)&als, g_als);
    cudaGetSymbolAddress((void**)&ald, g_ald);
    cudaGetSymbolAddress((void**)&src, g_src);
    cudaGetSymbolAddress((void**)&dst, g_dst);
    cudaGetSymbolAddress((void**)&deg, g_deg);
    cudaGetSymbolAddress((void**)&rowptr, g_rowptr);
    cudaGetSymbolAddress((void**)&cursor, g_cursor);
    cudaGetSymbolAddress((void**)&srcs, g_srcs);
    cudaGetSymbolAddress((void**)&eids, g_eids);
    cudaGetSymbolAddress((void**)&Ahb, g_Ah);
    cudaGetSymbolAddress((void**)&Alb, g_Al);
    cudaGetSymbolAddress((void**)&Bhb, g_Bh);
    cudaGetSymbolAddress((void**)&Blb, g_Bl);

    cudaFuncSetAttribute(gemm_mma_bf16x3, cudaFuncAttributeMaxDynamicSharedMemorySize, MM_SMEM);

    // ---- build CSR-by-dst ----
    fill_i<<<(NN + 255) / 256, 256>>>(deg, 0, NN);
    build_edges<<<(ET + 255) / 256, 256>>>(ei, src, dst, deg);
    scan_deg<<<1, 1024>>>(deg, rowptr, cursor);
    scatter_edges<<<(ET + 255) / 256, 256>>>(src, dst, cursor, srcs, eids);

    const float* X = x;
    for (int l = 0; l < 4; l++) {
        int H = Hh[l], C = Cc[l], D = H * C, K = din[l], NP = Npad[l];

        // split inputs + weights to bf16 hi/lo
        int nA = NN * K;
        convA<<<(nA + 255) / 256, 256>>>(X, Ahb, Alb, nA);
        dim3 tg(K / 32, NP / 32);
        convBT<<<tg, dim3(32, 8)>>>(W[l], Bhb, Blb, K, D);

        // tensor-core GEMM via mma.sync: bufH = X @ W
        dim3 gg(NP / 128, NN / 128);
        gemm_mma_bf16x3<<<gg, 256, MM_SMEM>>>(Ahb, Alb, Bhb, Blb, bufH, K, D);

        int warps = NN * H;
        attn_logits<<<(warps * 32 + 255) / 256, 256>>>(bufH, Asr[l], Ads[l], als, ald, H, C);

        fill_mz<<<(NN * H + 255) / 256, 256>>>(m, z, NN * H);
        edge_max<<<(ET * H + 255) / 256, 256>>>(als, ald, src, dst, m, H);
        edge_exp<<<(ET * H + 255) / 256, 256>>>(als, ald, src, dst, m, z, alpha, H);

        float* outp = (l == 3) ? (float*)d_out : bufO;
        aggregate<<<dim3(NN, H), 128>>>(bufH, alpha, z, rowptr, srcs, eids, Bi[l], outp,
                                        H, C, (l < 3) ? 1 : 0);
        if (l < 3) {
            ln_kernel<<<NN, 256>>>(bufO, G[l], Be[l], bufA, D);
            X = bufA;
        }
    }
}